// round 13
// baseline (speedup 1.0000x reference)
#include <cuda_runtime.h>
#include <math.h>

// Problem constants
#define MROWS   16384          // B*N = 32*512
#define DMODEL  512
#define HEADS   8
#define DEPTH   147
#define DH      1176           // HEADS*DEPTH
#define QKC     2352           // 2*DH
#define VSTRIDE 1184           // DH padded to multiple of 16 (GEMM3 K-loop)

// Scratch (static device globals — no runtime allocation)
__device__ float g_QK[(size_t)MROWS * QKC];      // fp32 q|k (attn input)
__device__ float g_V [(size_t)MROWS * VSTRIDE];  // tf32-bits V; pads zero
// tf32-rounded weights (pre-pass; same layouts as inputs)
__device__ float g_wq[(size_t)DMODEL * QKC];     // qk_w
__device__ float g_wv[(size_t)DMODEL * DH];      // v_w
__device__ float g_wl[(size_t)DH * DMODEL];      // lin_w

__device__ __forceinline__ unsigned f2tf(float x) {
    unsigned r;
    asm("cvt.rna.tf32.f32 %0, %1;" : "=r"(r) : "f"(x));
    return r;
}
__device__ __forceinline__ float f2tf_f(float x) {
    return __uint_as_float(f2tf(x));
}
__device__ __forceinline__ unsigned smem_u32(const void* p) {
    return (unsigned)__cvta_generic_to_shared(p);
}
#define CP_ASYNC16(dst_u32, src_ptr, bytes) \
    asm volatile("cp.async.cg.shared.global [%0], [%1], 16, %2;" \
                 :: "r"(dst_u32), "l"(src_ptr), "r"(bytes))
#define CP_COMMIT()  asm volatile("cp.async.commit_group;")
#define CP_WAIT(n)   asm volatile("cp.async.wait_group %0;" :: "n"(n))

// ---------------------------------------------------------------------------
// Pre-pass: tf32-round the 3 weight matrices (element counts mult of 4).
// ---------------------------------------------------------------------------
__global__ __launch_bounds__(256) void cvtw_kernel(
    const float* __restrict__ s0, float* __restrict__ d0, int n0,
    const float* __restrict__ s1, float* __restrict__ d1, int n1,
    const float* __restrict__ s2, float* __restrict__ d2, int n2)
{
    const float* s; float* d; int n;
    switch (blockIdx.y) {
        case 0:  s = s0; d = d0; n = n0; break;
        case 1:  s = s1; d = d1; n = n1; break;
        default: s = s2; d = d2; n = n2; break;
    }
    const int n4 = n >> 2;
    const int stride = gridDim.x * blockDim.x;
    for (int i = blockIdx.x * blockDim.x + threadIdx.x; i < n4; i += stride) {
        float4 v = ((const float4*)s)[i];
        uint4 u;
        u.x = f2tf(v.x); u.y = f2tf(v.y); u.z = f2tf(v.z); u.w = f2tf(v.w);
        ((uint4*)d)[i] = u;
    }
}

// ---------------------------------------------------------------------------
// TF32 tensor-core GEMM body: C[M,N] = A[M,K] @ B[K,N] (+ bias)
// B always holds tf32 BIT PATTERNS. A_TF: A also pre-rounded (no in-loop cvt).
// ROUND_C: store tf32-rounded bits to C (for V feeding GEMM3).
// Tile 128x128x16, 256 threads (8 warps 2x4), warp tile 64x32, m16n8k8.
// 5-stage cp.async pipeline (wait_group 3 => 3 fetches in flight).
// K multiple of 16; A reads always in-bounds;
// B zfilled by (k < KB, col < NB); C stores guarded by col < Nstore.
// ---------------------------------------------------------------------------
#define STAGES 5
#define ASTR   20     // 16+4 pad (floats); row offset 80B = 5*16 (cp.async ok)
#define BSTR   136    // 128+8 pad; k-row offset 544B; frag loads conflict-free
#define A_FLTS (128 * ASTR)            // 2560
#define B_FLTS (16 * BSTR)             // 2176
#define STAGE_FLTS (A_FLTS + B_FLTS)   // 4736
#define SMEM_BYTES (STAGES * STAGE_FLTS * 4)   // 94720

template <bool HAS_BIAS, bool A_TF, bool ROUND_C>
__device__ __forceinline__ void gemm_body(
    const float* __restrict__ A, const float* __restrict__ B,
    float* __restrict__ C, const float* __restrict__ bias,
    int K, int lda, int ldb, int ldc, int NB, int KB, int Nstore,
    int row0, int col0)
{
    extern __shared__ float smem[];

    const int tid  = threadIdx.x;
    const int wid  = tid >> 5;
    const int lane = tid & 31;
    const int gp   = lane >> 2;
    const int tg   = lane & 3;
    const int warp_m = (wid & 1) * 64;
    const int warp_n = (wid >> 1) * 32;

    const int arow0 = tid >> 2, ak4 = (tid & 3) << 2;   // + i*64 rows
    const int bkr0  = tid >> 5, bc4 = (tid & 31) << 2;  // + i*8  k-rows

    auto issue_stage = [&](int s, int k0) {
        float* sA = smem + s * STAGE_FLTS;
        float* sB = sA + A_FLTS;
        #pragma unroll
        for (int i = 0; i < 2; i++) {
            int arow = arow0 + i * 64;
            CP_ASYNC16(smem_u32(sA + arow * ASTR + ak4),
                       A + (size_t)(row0 + arow) * lda + k0 + ak4, 16);
            int gk = k0 + bkr0 + i * 8;
            int gc = col0 + bc4;
            int rem = NB - gc;
            int valid = (gk < KB) ? (rem >= 4 ? 16 : (rem > 0 ? rem * 4 : 0)) : 0;
            int gkc = (gk < KB) ? gk : 0;
            int gcc = (valid > 0) ? gc : 0;
            CP_ASYNC16(smem_u32(sB + (bkr0 + i * 8) * BSTR + bc4),
                       B + (size_t)gkc * ldb + gcc, valid);
        }
        CP_COMMIT();
    };

    float acc[4][4][4];
    #pragma unroll
    for (int mt = 0; mt < 4; mt++)
        #pragma unroll
        for (int nt = 0; nt < 4; nt++)
            #pragma unroll
            for (int r = 0; r < 4; r++) acc[mt][nt][r] = 0.f;

    const int k_tiles = K / 16;
    int fetch = 0;
    for (; fetch < STAGES - 1; fetch++)          // k_tiles >= 32 always here
        issue_stage(fetch, fetch * 16);
    CP_WAIT(STAGES - 2);
    __syncthreads();

    int cur = 0;
    for (int it = 0; it < k_tiles; it++) {
        if (fetch < k_tiles) {
            issue_stage(fetch % STAGES, fetch * 16);
            fetch++;
        } else {
            CP_COMMIT();   // keep group counts aligned
        }

        const float*    sAf = smem + cur * STAGE_FLTS;
        const unsigned* sAu = (const unsigned*)sAf;
        const unsigned* sB  = (const unsigned*)(sAf + A_FLTS);
        #pragma unroll
        for (int ks = 0; ks < 2; ks++) {
            unsigned af[4][4], bf[4][2];
            #pragma unroll
            for (int mt = 0; mt < 4; mt++) {
                const int boff = (warp_m + mt * 16 + gp) * ASTR + ks * 8 + tg;
                if (A_TF) {
                    af[mt][0] = sAu[boff];
                    af[mt][1] = sAu[boff + 8 * ASTR];
                    af[mt][2] = sAu[boff + 4];
                    af[mt][3] = sAu[boff + 8 * ASTR + 4];
                } else {
                    af[mt][0] = f2tf(sAf[boff]);
                    af[mt][1] = f2tf(sAf[boff + 8 * ASTR]);
                    af[mt][2] = f2tf(sAf[boff + 4]);
                    af[mt][3] = f2tf(sAf[boff + 8 * ASTR + 4]);
                }
            }
            #pragma unroll
            for (int nt = 0; nt < 4; nt++) {
                const unsigned* base = sB + (ks * 8 + tg) * BSTR + warp_n + nt * 8 + gp;
                bf[nt][0] = base[0];           // pre-rounded tf32 bits
                bf[nt][1] = base[4 * BSTR];
            }
            #pragma unroll
            for (int mt = 0; mt < 4; mt++)
                #pragma unroll
                for (int nt = 0; nt < 4; nt++) {
                    asm volatile(
                        "mma.sync.aligned.m16n8k8.row.col.f32.tf32.tf32.f32 "
                        "{%0,%1,%2,%3}, {%4,%5,%6,%7}, {%8,%9}, {%0,%1,%2,%3};"
                        : "+f"(acc[mt][nt][0]), "+f"(acc[mt][nt][1]),
                          "+f"(acc[mt][nt][2]), "+f"(acc[mt][nt][3])
                        : "r"(af[mt][0]), "r"(af[mt][1]),
                          "r"(af[mt][2]), "r"(af[mt][3]),
                          "r"(bf[nt][0]), "r"(bf[nt][1]));
                }
        }

        CP_WAIT(STAGES - 2);
        __syncthreads();
        cur = (cur + 1) % STAGES;
        if (cur == STAGES) cur = 0;
    }

    // Epilogue
    const bool full = (col0 + 128) <= Nstore;
    #pragma unroll
    for (int mt = 0; mt < 4; mt++) {
        #pragma unroll
        for (int half = 0; half < 2; half++) {
            int r = row0 + warp_m + mt * 16 + gp + half * 8;
            float* crow = C + (size_t)r * ldc;
            #pragma unroll
            for (int nt = 0; nt < 4; nt++) {
                int c  = col0 + warp_n + nt * 8 + tg * 2;
                float v0 = acc[mt][nt][half * 2 + 0];
                float v1 = acc[mt][nt][half * 2 + 1];
                if (HAS_BIAS) { v0 += bias ? bias[c] : 0.f; v1 += bias ? bias[c + 1] : 0.f; }
                if (ROUND_C) { v0 = f2tf_f(v0); v1 = f2tf_f(v1); }
                if (full) {
                    *(float2*)(crow + c) = make_float2(v0, v1);
                } else {
                    if (c < Nstore)     crow[c]     = v0;
                    if (c + 1 < Nstore) crow[c + 1] = v1;
                }
            }
        }
    }
}

// Merged GEMM1 + GEMM2 (one launch => one ragged wave-tail)
__global__ __launch_bounds__(256, 2) void qkv_gemm_kernel(
    const float* __restrict__ query, const float* __restrict__ value,
    const float* __restrict__ wq,  const float* __restrict__ wv,
    float* __restrict__ QK, float* __restrict__ V)
{
    const int x = blockIdx.x;
    const int row0 = blockIdx.y * 128;
    if (x < 19) {   // GEMM1: QK = query @ qk_w  [16384,512]@[512,2352], fp32 out
        gemm_body<false, false, false>(query, wq, QK, nullptr,
                         512, 512, QKC, QKC, QKC, 512, QKC,
                         row0, x * 128);
    } else {        // GEMM2: V = value @ v_w -> tf32-rounded bits, pad 1184
        gemm_body<false, false, true>(value, wv, V, nullptr,
                         512, 512, DH, VSTRIDE, DH, 512, VSTRIDE,
                         row0, (x - 19) * 128);
    }
}

// GEMM3: out = V @ lin_w + b; A pre-rounded (no in-loop cvt); N=512 unguarded
__global__ __launch_bounds__(256, 2) void out_gemm_kernel(
    const float* __restrict__ V, const float* __restrict__ wl,
    float* __restrict__ out, const float* __restrict__ lin_b)
{
    gemm_body<true, true, false>(V, wl, out, lin_b,
                    VSTRIDE, VSTRIDE, DMODEL, DMODEL, DMODEL, DH, DMODEL,
                    blockIdx.y * 128, blockIdx.x * 128);
}

// ---------------------------------------------------------------------------
// Tiny per-frame attention, register-resident probs + vectorized smem.
// One warp per (m,h); lane r (r<24) owns prob row r in registers.
// In-place update of g_V[m, h*147+3 .. +146], written as tf32-rounded bits.
// ---------------------------------------------------------------------------
__global__ __launch_bounds__(256) void attn_kernel(
    const float* __restrict__ QK, float* __restrict__ V)
{
    const int warp = threadIdx.x >> 5;
    const int lane = threadIdx.x & 31;
    const int f = blockIdx.x * 8 + warp;
    const int m = f >> 3;
    const int h = f & 7;

    __shared__ float sq8[8][192];   // q (padded rows of 8); reused as out staging
    __shared__ float sk8[8][192];   // k padded
    __shared__ float sv8[8][192];   // v padded

    float* q8 = sq8[warp];
    float* k8 = sk8[warp];
    float* v8 = sv8[warp];

    const float* qrow = QK + (size_t)m * QKC + h * DEPTH + 3;
    const float* krow = QK + (size_t)m * QKC + DH + h * DEPTH + 3;
    float*       vrow = V  + (size_t)m * VSTRIDE + h * DEPTH + 3;

    for (int i = lane; i < 144; i += 32) {
        int r = i / 6, c = i - r * 6;
        q8[r * 8 + c] = qrow[i];
        k8[r * 8 + c] = krow[i];
        v8[r * 8 + c] = vrow[i];
    }
    __syncwarp();

    const float scale = 0.4082482904638630f;  // 1/sqrt(6)
    const bool act = (lane < 24);
    float s[24];

    if (act) {
        float4 q03 = *(const float4*)(q8 + lane * 8);
        float2 q45 = *(const float2*)(q8 + lane * 8 + 4);
        #pragma unroll
        for (int c = 0; c < 24; c++) {
            float4 k03 = *(const float4*)(k8 + c * 8);
            float2 k45 = *(const float2*)(k8 + c * 8 + 4);
            float a = q03.x * k03.x;
            a = fmaf(q03.y, k03.y, a);
            a = fmaf(q03.z, k03.z, a);
            a = fmaf(q03.w, k03.w, a);
            a = fmaf(q45.x, k45.x, a);
            a = fmaf(q45.y, k45.y, a);
            s[c] = a * scale;
        }
        float mx = s[0];
        #pragma unroll
        for (int c = 1; c < 24; c++) mx = fmaxf(mx, s[c]);
        float sum = 0.f;
        #pragma unroll
        for (int c = 0; c < 24; c++) {
            s[c] = __expf(s[c] - mx);
            sum += s[c];
        }
        float inv = 1.0f / sum;
        #pragma unroll
        for (int c = 0; c < 24; c++) s[c] *= inv;
    } else {
        #pragma unroll
        for (int c = 0; c < 24; c++) s[c] = 0.f;
    }

    // Row-0 averaging chain: p[0][*] entirely in lane 0's registers.
    if (lane == 0) {
        s[6]  = (s[6]  + s[3])  * 0.5f;
        s[9]  = (s[9]  + s[6])  * 0.5f;
        s[12] = (s[12] + s[9])  * 0.5f;
        s[13] = (s[13] + s[9])  * 0.5f;
        s[14] = (s[14] + s[9])  * 0.5f;
        s[16] = (s[16] + s[13]) * 0.5f;
        s[17] = (s[17] + s[14]) * 0.5f;
        s[15] = (s[15] + s[12]) * 0.5f;
    }
    // Col-0 chain: p[r][0] = s[0] of lane r; sequential deps via shuffles.
    {
        float c0 = s[0];
        float t;
        t = __shfl_sync(0xffffffffu, c0, 3);
        if (lane == 6)  c0 = (c0 + t) * 0.5f;
        t = __shfl_sync(0xffffffffu, c0, 6);
        if (lane == 9)  c0 = (c0 + t) * 0.5f;
        t = __shfl_sync(0xffffffffu, c0, 9);
        if (lane >= 12 && lane <= 14) c0 = (c0 + t) * 0.5f;
        int src = (lane >= 15 && lane <= 17) ? (lane - 3) : 0;
        t = __shfl_sync(0xffffffffu, c0, src);
        if (lane >= 15 && lane <= 17) c0 = (c0 + t) * 0.5f;
        s[0] = c0;
    }

    __syncwarp();   // all q8 reads done before reusing sq8 as out staging

    // attn out row `lane`: acc[d] = sum_k s[k] * v[k][d]; 2 vector LDS per k
    if (act) {
        float a0 = 0.f, a1 = 0.f, a2 = 0.f, a3 = 0.f, a4 = 0.f, a5 = 0.f;
        #pragma unroll
        for (int kk = 0; kk < 24; kk++) {
            float4 v03 = *(const float4*)(v8 + kk * 8);
            float2 v45 = *(const float2*)(v8 + kk * 8 + 4);
            float w = s[kk];
            a0 = fmaf(w, v03.x, a0);
            a1 = fmaf(w, v03.y, a1);
            a2 = fmaf(w, v03.z, a2);
            a3 = fmaf(w, v03.w, a3);
            a4 = fmaf(w, v45.x, a4);
            a5 = fmaf(w, v45.y, a5);
        }
        float* o = q8 + lane * 6;    // contiguous 144-float staging
        o[0] = f2tf_f(a0); o[1] = f2tf_f(a1); o[2] = f2tf_f(a2);
        o[3] = f2tf_f(a3); o[4] = f2tf_f(a4); o[5] = f2tf_f(a5);
    }
    __syncwarp();

    for (int e = lane; e < 144; e += 32) vrow[e] = q8[e];
}

// ---------------------------------------------------------------------------
// Entry point
// ---------------------------------------------------------------------------
extern "C" void kernel_launch(void* const* d_in, const int* in_sizes, int n_in,
                              void* d_out, int out_size)
{
    const float* query = (const float*)d_in[0];
    // d_in[1] = key: intentionally unused (reference ignores it)
    const float* value = (const float*)d_in[2];
    const float* qk_w  = (const float*)d_in[3];
    const float* v_w   = (const float*)d_in[4];
    const float* lin_w = (const float*)d_in[5];
    const float* lin_b = (const float*)d_in[6];
    float* out = (float*)d_out;

    static float *QK = nullptr, *V, *wq, *wv, *wl;
    if (!QK) {
        cudaGetSymbolAddress((void**)&QK, g_QK);
        cudaGetSymbolAddress((void**)&V,  g_V);
        cudaGetSymbolAddress((void**)&wq, g_wq);
        cudaGetSymbolAddress((void**)&wv, g_wv);
        cudaGetSymbolAddress((void**)&wl, g_wl);
        cudaFuncSetAttribute(qkv_gemm_kernel,
                             cudaFuncAttributeMaxDynamicSharedMemorySize, SMEM_BYTES);
        cudaFuncSetAttribute(out_gemm_kernel,
                             cudaFuncAttributeMaxDynamicSharedMemorySize, SMEM_BYTES);
    }

    dim3 blk(256);

    // Pre-pass: tf32-round the weights (cheap: ~2.4M elems)
    cvtw_kernel<<<dim3(64, 3), blk>>>(
        qk_w, wq, DMODEL * QKC,
        v_w,  wv, DMODEL * DH,
        lin_w, wl, DH * DMODEL);

    // GEMM1 + GEMM2 fused launch (19 + 10 column tiles)
    qkv_gemm_kernel<<<dim3(29, MROWS / 128), blk, SMEM_BYTES>>>(
        query, value, wq, wv, QK, V);

    // Tiny attention, in-place on V (one warp per (m,h))
    attn_kernel<<<(MROWS * HEADS) / 8, 256>>>(QK, V);

    // GEMM3 (A pre-rounded bits)
    out_gemm_kernel<<<dim3(DMODEL / 128, MROWS / 128), blk, SMEM_BYTES>>>(
        V, wl, out, lin_b);
}

// round 14
// speedup vs baseline: 1.1073x; 1.1073x over previous
#include <cuda_runtime.h>
#include <math.h>

// Problem constants
#define MROWS   16384          // B*N = 32*512
#define DMODEL  512
#define HEADS   8
#define DEPTH   147
#define DH      1176           // HEADS*DEPTH
#define QKC     2352           // 2*DH
#define VSTRIDE 1184           // DH padded to multiple of 32 (GEMM3 K-loop)

// Scratch (static device globals — no runtime allocation)
__device__ float g_QK[(size_t)MROWS * QKC];      // fp32 q|k (attn input)
__device__ float g_V [(size_t)MROWS * VSTRIDE];  // tf32-bits V; pads zero
// tf32-rounded weights (pre-pass; same layouts as inputs)
__device__ float g_wq[(size_t)DMODEL * QKC];     // qk_w
__device__ float g_wv[(size_t)DMODEL * DH];      // v_w
__device__ float g_wl[(size_t)DH * DMODEL];      // lin_w

__device__ __forceinline__ unsigned f2tf(float x) {
    unsigned r;
    asm("cvt.rna.tf32.f32 %0, %1;" : "=r"(r) : "f"(x));
    return r;
}
__device__ __forceinline__ float f2tf_f(float x) {
    return __uint_as_float(f2tf(x));
}
__device__ __forceinline__ unsigned smem_u32(const void* p) {
    return (unsigned)__cvta_generic_to_shared(p);
}
#define CP_ASYNC16(dst_u32, src_ptr, bytes) \
    asm volatile("cp.async.cg.shared.global [%0], [%1], 16, %2;" \
                 :: "r"(dst_u32), "l"(src_ptr), "r"(bytes))
#define CP_COMMIT()  asm volatile("cp.async.commit_group;")
#define CP_WAIT(n)   asm volatile("cp.async.wait_group %0;" :: "n"(n))

// ---------------------------------------------------------------------------
// Pre-pass: tf32-round the 3 weight matrices (element counts mult of 4).
// ---------------------------------------------------------------------------
__global__ __launch_bounds__(256) void cvtw_kernel(
    const float* __restrict__ s0, float* __restrict__ d0, int n0,
    const float* __restrict__ s1, float* __restrict__ d1, int n1,
    const float* __restrict__ s2, float* __restrict__ d2, int n2)
{
    const float* s; float* d; int n;
    switch (blockIdx.y) {
        case 0:  s = s0; d = d0; n = n0; break;
        case 1:  s = s1; d = d1; n = n1; break;
        default: s = s2; d = d2; n = n2; break;
    }
    const int n4 = n >> 2;
    const int stride = gridDim.x * blockDim.x;
    for (int i = blockIdx.x * blockDim.x + threadIdx.x; i < n4; i += stride) {
        float4 v = ((const float4*)s)[i];
        uint4 u;
        u.x = f2tf(v.x); u.y = f2tf(v.y); u.z = f2tf(v.z); u.w = f2tf(v.w);
        ((uint4*)d)[i] = u;
    }
}

// ---------------------------------------------------------------------------
// TF32 tensor-core GEMM body: C[M,N] = A[M,K] @ B[K,N] (+ bias)
// B always holds tf32 BIT PATTERNS. A_TF: A also pre-rounded (no in-loop cvt).
// ROUND_C: store tf32-rounded bits to C (for V feeding GEMM3).
// Tile 128x128x32 (BK=32 => half the barriers of BK=16), 256 threads
// (8 warps 2x4), warp tile 64x32, m16n8k8, 4 k-steps per iteration.
// 3-stage cp.async pipeline. K multiple of 32; A reads always in-bounds;
// B zfilled by (k < KB, col < NB); C stores guarded by col < Nstore.
// ---------------------------------------------------------------------------
#define STAGES 3
#define ASTR   36     // 32+4 pad (floats); row stride 144B = 9*16 (cp.async ok)
#define BSTR   136    // 128+8 pad; k-row stride 544B; frag loads conflict-free
#define A_FLTS (128 * ASTR)            // 4608
#define B_FLTS (32 * BSTR)             // 4352
#define STAGE_FLTS (A_FLTS + B_FLTS)   // 8960
#define SMEM_BYTES (STAGES * STAGE_FLTS * 4)   // 107520

template <bool HAS_BIAS, bool A_TF, bool ROUND_C>
__device__ __forceinline__ void gemm_body(
    const float* __restrict__ A, const float* __restrict__ B,
    float* __restrict__ C, const float* __restrict__ bias,
    int K, int lda, int ldb, int ldc, int NB, int KB, int Nstore,
    int row0, int col0)
{
    extern __shared__ float smem[];

    const int tid  = threadIdx.x;
    const int wid  = tid >> 5;
    const int lane = tid & 31;
    const int gp   = lane >> 2;
    const int tg   = lane & 3;
    const int warp_m = (wid & 1) * 64;
    const int warp_n = (wid >> 1) * 32;

    // Per-stage loads: A = 128 rows x 8 chunks, B = 32 k-rows x 32 chunks;
    // 1024 chunks each => 4 A-chunks + 4 B-chunks per thread.
    auto issue_stage = [&](int s, int k0) {
        float* sA = smem + s * STAGE_FLTS;
        float* sB = sA + A_FLTS;
        #pragma unroll
        for (int i = 0; i < 4; i++) {
            int c = tid + i * 256;
            // A chunk: row = c>>3, col = (c&7)*4
            int arow = c >> 3, acol = (c & 7) << 2;
            CP_ASYNC16(smem_u32(sA + arow * ASTR + acol),
                       A + (size_t)(row0 + arow) * lda + k0 + acol, 16);
            // B chunk: k-row = c>>5, col = (c&31)*4
            int bkr = c >> 5, bc4 = (c & 31) << 2;
            int gk = k0 + bkr;
            int gc = col0 + bc4;
            int rem = NB - gc;
            int valid = (gk < KB) ? (rem >= 4 ? 16 : (rem > 0 ? rem * 4 : 0)) : 0;
            int gkc = (gk < KB) ? gk : 0;
            int gcc = (valid > 0) ? gc : 0;
            CP_ASYNC16(smem_u32(sB + bkr * BSTR + bc4),
                       B + (size_t)gkc * ldb + gcc, valid);
        }
        CP_COMMIT();
    };

    float acc[4][4][4];
    #pragma unroll
    for (int mt = 0; mt < 4; mt++)
        #pragma unroll
        for (int nt = 0; nt < 4; nt++)
            #pragma unroll
            for (int r = 0; r < 4; r++) acc[mt][nt][r] = 0.f;

    const int k_tiles = K / 32;
    int fetch = 0;
    for (; fetch < STAGES - 1; fetch++)          // k_tiles >= 16 always here
        issue_stage(fetch, fetch * 32);
    CP_WAIT(STAGES - 2);
    __syncthreads();

    int cur = 0;
    for (int it = 0; it < k_tiles; it++) {
        if (fetch < k_tiles) {
            issue_stage(fetch % STAGES, fetch * 32);
            fetch++;
        } else {
            CP_COMMIT();   // keep group counts aligned
        }

        const float*    sAf = smem + cur * STAGE_FLTS;
        const unsigned* sAu = (const unsigned*)sAf;
        const unsigned* sB  = (const unsigned*)(sAf + A_FLTS);
        #pragma unroll
        for (int ks = 0; ks < 4; ks++) {
            unsigned af[4][4], bf[4][2];
            #pragma unroll
            for (int mt = 0; mt < 4; mt++) {
                const int boff = (warp_m + mt * 16 + gp) * ASTR + ks * 8 + tg;
                if (A_TF) {
                    af[mt][0] = sAu[boff];
                    af[mt][1] = sAu[boff + 8 * ASTR];
                    af[mt][2] = sAu[boff + 4];
                    af[mt][3] = sAu[boff + 8 * ASTR + 4];
                } else {
                    af[mt][0] = f2tf(sAf[boff]);
                    af[mt][1] = f2tf(sAf[boff + 8 * ASTR]);
                    af[mt][2] = f2tf(sAf[boff + 4]);
                    af[mt][3] = f2tf(sAf[boff + 8 * ASTR + 4]);
                }
            }
            #pragma unroll
            for (int nt = 0; nt < 4; nt++) {
                const unsigned* base = sB + (ks * 8 + tg) * BSTR + warp_n + nt * 8 + gp;
                bf[nt][0] = base[0];           // pre-rounded tf32 bits
                bf[nt][1] = base[4 * BSTR];
            }
            #pragma unroll
            for (int mt = 0; mt < 4; mt++)
                #pragma unroll
                for (int nt = 0; nt < 4; nt++) {
                    asm volatile(
                        "mma.sync.aligned.m16n8k8.row.col.f32.tf32.tf32.f32 "
                        "{%0,%1,%2,%3}, {%4,%5,%6,%7}, {%8,%9}, {%0,%1,%2,%3};"
                        : "+f"(acc[mt][nt][0]), "+f"(acc[mt][nt][1]),
                          "+f"(acc[mt][nt][2]), "+f"(acc[mt][nt][3])
                        : "r"(af[mt][0]), "r"(af[mt][1]),
                          "r"(af[mt][2]), "r"(af[mt][3]),
                          "r"(bf[nt][0]), "r"(bf[nt][1]));
                }
        }

        CP_WAIT(STAGES - 2);
        __syncthreads();
        cur = cur + 1;
        if (cur == STAGES) cur = 0;
    }

    // Epilogue
    const bool full = (col0 + 128) <= Nstore;
    #pragma unroll
    for (int mt = 0; mt < 4; mt++) {
        #pragma unroll
        for (int half = 0; half < 2; half++) {
            int r = row0 + warp_m + mt * 16 + gp + half * 8;
            float* crow = C + (size_t)r * ldc;
            #pragma unroll
            for (int nt = 0; nt < 4; nt++) {
                int c  = col0 + warp_n + nt * 8 + tg * 2;
                float v0 = acc[mt][nt][half * 2 + 0];
                float v1 = acc[mt][nt][half * 2 + 1];
                if (HAS_BIAS) { v0 += bias ? bias[c] : 0.f; v1 += bias ? bias[c + 1] : 0.f; }
                if (ROUND_C) { v0 = f2tf_f(v0); v1 = f2tf_f(v1); }
                if (full) {
                    *(float2*)(crow + c) = make_float2(v0, v1);
                } else {
                    if (c < Nstore)     crow[c]     = v0;
                    if (c + 1 < Nstore) crow[c + 1] = v1;
                }
            }
        }
    }
}

// Merged GEMM1 + GEMM2 (one launch => one ragged wave-tail)
__global__ __launch_bounds__(256, 2) void qkv_gemm_kernel(
    const float* __restrict__ query, const float* __restrict__ value,
    const float* __restrict__ wq,  const float* __restrict__ wv,
    float* __restrict__ QK, float* __restrict__ V)
{
    const int x = blockIdx.x;
    const int row0 = blockIdx.y * 128;
    if (x < 19) {   // GEMM1: QK = query @ qk_w  [16384,512]@[512,2352], fp32 out
        gemm_body<false, false, false>(query, wq, QK, nullptr,
                         512, 512, QKC, QKC, QKC, 512, QKC,
                         row0, x * 128);
    } else {        // GEMM2: V = value @ v_w -> tf32-rounded bits, pad 1184
        gemm_body<false, false, true>(value, wv, V, nullptr,
                         512, 512, DH, VSTRIDE, DH, 512, VSTRIDE,
                         row0, (x - 19) * 128);
    }
}

// GEMM3: out = V @ lin_w + b; A pre-rounded (no in-loop cvt); N=512 unguarded
__global__ __launch_bounds__(256, 2) void out_gemm_kernel(
    const float* __restrict__ V, const float* __restrict__ wl,
    float* __restrict__ out, const float* __restrict__ lin_b)
{
    gemm_body<true, true, false>(V, wl, out, lin_b,
                    VSTRIDE, VSTRIDE, DMODEL, DMODEL, DMODEL, DH, DMODEL,
                    blockIdx.y * 128, blockIdx.x * 128);
}

// ---------------------------------------------------------------------------
// Tiny per-frame attention, register-resident probs + vectorized smem.
// One warp per (m,h); lane r (r<24) owns prob row r in registers.
// In-place update of g_V[m, h*147+3 .. +146], written as tf32-rounded bits.
// ---------------------------------------------------------------------------
__global__ __launch_bounds__(256) void attn_kernel(
    const float* __restrict__ QK, float* __restrict__ V)
{
    const int warp = threadIdx.x >> 5;
    const int lane = threadIdx.x & 31;
    const int f = blockIdx.x * 8 + warp;
    const int m = f >> 3;
    const int h = f & 7;

    __shared__ float sq8[8][192];   // q (padded rows of 8); reused as out staging
    __shared__ float sk8[8][192];   // k padded
    __shared__ float sv8[8][192];   // v padded

    float* q8 = sq8[warp];
    float* k8 = sk8[warp];
    float* v8 = sv8[warp];

    const float* qrow = QK + (size_t)m * QKC + h * DEPTH + 3;
    const float* krow = QK + (size_t)m * QKC + DH + h * DEPTH + 3;
    float*       vrow = V  + (size_t)m * VSTRIDE + h * DEPTH + 3;

    for (int i = lane; i < 144; i += 32) {
        int r = i / 6, c = i - r * 6;
        q8[r * 8 + c] = qrow[i];
        k8[r * 8 + c] = krow[i];
        v8[r * 8 + c] = vrow[i];
    }
    __syncwarp();

    const float scale = 0.4082482904638630f;  // 1/sqrt(6)
    const bool act = (lane < 24);
    float s[24];

    if (act) {
        float4 q03 = *(const float4*)(q8 + lane * 8);
        float2 q45 = *(const float2*)(q8 + lane * 8 + 4);
        #pragma unroll
        for (int c = 0; c < 24; c++) {
            float4 k03 = *(const float4*)(k8 + c * 8);
            float2 k45 = *(const float2*)(k8 + c * 8 + 4);
            float a = q03.x * k03.x;
            a = fmaf(q03.y, k03.y, a);
            a = fmaf(q03.z, k03.z, a);
            a = fmaf(q03.w, k03.w, a);
            a = fmaf(q45.x, k45.x, a);
            a = fmaf(q45.y, k45.y, a);
            s[c] = a * scale;
        }
        float mx = s[0];
        #pragma unroll
        for (int c = 1; c < 24; c++) mx = fmaxf(mx, s[c]);
        float sum = 0.f;
        #pragma unroll
        for (int c = 0; c < 24; c++) {
            s[c] = __expf(s[c] - mx);
            sum += s[c];
        }
        float inv = 1.0f / sum;
        #pragma unroll
        for (int c = 0; c < 24; c++) s[c] *= inv;
    } else {
        #pragma unroll
        for (int c = 0; c < 24; c++) s[c] = 0.f;
    }

    // Row-0 averaging chain: p[0][*] entirely in lane 0's registers.
    if (lane == 0) {
        s[6]  = (s[6]  + s[3])  * 0.5f;
        s[9]  = (s[9]  + s[6])  * 0.5f;
        s[12] = (s[12] + s[9])  * 0.5f;
        s[13] = (s[13] + s[9])  * 0.5f;
        s[14] = (s[14] + s[9])  * 0.5f;
        s[16] = (s[16] + s[13]) * 0.5f;
        s[17] = (s[17] + s[14]) * 0.5f;
        s[15] = (s[15] + s[12]) * 0.5f;
    }
    // Col-0 chain: p[r][0] = s[0] of lane r; sequential deps via shuffles.
    {
        float c0 = s[0];
        float t;
        t = __shfl_sync(0xffffffffu, c0, 3);
        if (lane == 6)  c0 = (c0 + t) * 0.5f;
        t = __shfl_sync(0xffffffffu, c0, 6);
        if (lane == 9)  c0 = (c0 + t) * 0.5f;
        t = __shfl_sync(0xffffffffu, c0, 9);
        if (lane >= 12 && lane <= 14) c0 = (c0 + t) * 0.5f;
        int src = (lane >= 15 && lane <= 17) ? (lane - 3) : 0;
        t = __shfl_sync(0xffffffffu, c0, src);
        if (lane >= 15 && lane <= 17) c0 = (c0 + t) * 0.5f;
        s[0] = c0;
    }

    __syncwarp();   // all q8 reads done before reusing sq8 as out staging

    // attn out row `lane`: acc[d] = sum_k s[k] * v[k][d]; 2 vector LDS per k
    if (act) {
        float a0 = 0.f, a1 = 0.f, a2 = 0.f, a3 = 0.f, a4 = 0.f, a5 = 0.f;
        #pragma unroll
        for (int kk = 0; kk < 24; kk++) {
            float4 v03 = *(const float4*)(v8 + kk * 8);
            float2 v45 = *(const float2*)(v8 + kk * 8 + 4);
            float w = s[kk];
            a0 = fmaf(w, v03.x, a0);
            a1 = fmaf(w, v03.y, a1);
            a2 = fmaf(w, v03.z, a2);
            a3 = fmaf(w, v03.w, a3);
            a4 = fmaf(w, v45.x, a4);
            a5 = fmaf(w, v45.y, a5);
        }
        float* o = q8 + lane * 6;    // contiguous 144-float staging
        o[0] = f2tf_f(a0); o[1] = f2tf_f(a1); o[2] = f2tf_f(a2);
        o[3] = f2tf_f(a3); o[4] = f2tf_f(a4); o[5] = f2tf_f(a5);
    }
    __syncwarp();

    for (int e = lane; e < 144; e += 32) vrow[e] = q8[e];
}

// ---------------------------------------------------------------------------
// Entry point
// ---------------------------------------------------------------------------
extern "C" void kernel_launch(void* const* d_in, const int* in_sizes, int n_in,
                              void* d_out, int out_size)
{
    const float* query = (const float*)d_in[0];
    // d_in[1] = key: intentionally unused (reference ignores it)
    const float* value = (const float*)d_in[2];
    const float* qk_w  = (const float*)d_in[3];
    const float* v_w   = (const float*)d_in[4];
    const float* lin_w = (const float*)d_in[5];
    const float* lin_b = (const float*)d_in[6];
    float* out = (float*)d_out;

    static float *QK = nullptr, *V, *wq, *wv, *wl;
    if (!QK) {
        cudaGetSymbolAddress((void**)&QK, g_QK);
        cudaGetSymbolAddress((void**)&V,  g_V);
        cudaGetSymbolAddress((void**)&wq, g_wq);
        cudaGetSymbolAddress((void**)&wv, g_wv);
        cudaGetSymbolAddress((void**)&wl, g_wl);
        cudaFuncSetAttribute(qkv_gemm_kernel,
                             cudaFuncAttributeMaxDynamicSharedMemorySize, SMEM_BYTES);
        cudaFuncSetAttribute(out_gemm_kernel,
                             cudaFuncAttributeMaxDynamicSharedMemorySize, SMEM_BYTES);
    }

    dim3 blk(256);

    // Pre-pass: tf32-round the weights (cheap: ~2.4M elems)
    cvtw_kernel<<<dim3(64, 3), blk>>>(
        qk_w, wq, DMODEL * QKC,
        v_w,  wv, DMODEL * DH,
        lin_w, wl, DH * DMODEL);

    // GEMM1 + GEMM2 fused launch (19 + 10 column tiles)
    qkv_gemm_kernel<<<dim3(29, MROWS / 128), blk, SMEM_BYTES>>>(
        query, value, wq, wv, QK, V);

    // Tiny attention, in-place on V (one warp per (m,h))
    attn_kernel<<<(MROWS * HEADS) / 8, 256>>>(QK, V);

    // GEMM3 (A pre-rounded bits)
    out_gemm_kernel<<<dim3(DMODEL / 128, MROWS / 128), blk, SMEM_BYTES>>>(
        V, wl, out, lin_b);
}